// round 3
// baseline (speedup 1.0000x reference)
#include <cuda_runtime.h>
#include <math.h>

#define BB 4
#define NN 2048
#define CC 256
#define HH 16
#define DD 16

// Scratch (allocation-free rule: __device__ globals)
__device__ float g_q[BB * HH * NN * DD];   // 8 MB
__device__ float g_k[BB * HH * NN * DD];   // 8 MB
__device__ float g_v[BB * HH * NN * DD];   // 8 MB
__device__ float g_o[BB * NN * CC];        // 8 MB (attention output, (B,N,C) layout)

// ---------------------------------------------------------------------------
// Tiled SGEMM 64x64x16, 256 threads, 4x4 microtile.
// QKV variant scatters into g_q/g_k/g_v with (B,H,N,D) layout.
// ---------------------------------------------------------------------------
__global__ void gemm_qkv_kernel(const float* __restrict__ A,
                                const float* __restrict__ W,
                                const float* __restrict__ bias) {
    const int K = CC;        // 256
    const int Nn = 3 * CC;   // 768
    __shared__ float As[16][64];
    __shared__ float Bs[16][64];
    int tid = threadIdx.x;
    int tx = tid & 15, ty = tid >> 4;
    int m0 = blockIdx.y * 64, n0 = blockIdx.x * 64;
    int ar = tid >> 2, ac = (tid & 3) << 2;   // A tile load: 64 rows x 16 cols
    int br = tid >> 4, bc = (tid & 15) << 2;  // B tile load: 16 rows x 64 cols
    float acc[4][4] = {};
    for (int k0 = 0; k0 < K; k0 += 16) {
        float4 a = *(const float4*)&A[(size_t)(m0 + ar) * K + k0 + ac];
        As[ac + 0][ar] = a.x; As[ac + 1][ar] = a.y;
        As[ac + 2][ar] = a.z; As[ac + 3][ar] = a.w;
        *(float4*)&Bs[br][bc] = *(const float4*)&W[(size_t)(k0 + br) * Nn + n0 + bc];
        __syncthreads();
#pragma unroll
        for (int k = 0; k < 16; k++) {
            float ra[4], rb[4];
            *(float4*)ra = *(const float4*)&As[k][ty * 4];
            *(float4*)rb = *(const float4*)&Bs[k][tx * 4];
#pragma unroll
            for (int i = 0; i < 4; i++)
#pragma unroll
                for (int j = 0; j < 4; j++)
                    acc[i][j] += ra[i] * rb[j];
        }
        __syncthreads();
    }
    // Scatter epilogue: col n in [0,768): t = n/256 selects q/k/v;
    // within: h = (n%256)/16, d = n%16.  row m: b = m/2048, nq = m%2048.
#pragma unroll
    for (int i = 0; i < 4; i++) {
        int m = m0 + ty * 4 + i;
        int b = m >> 11;
        int nq = m & 2047;
#pragma unroll
        for (int j = 0; j < 4; j++) {
            int n = n0 + tx * 4 + j;
            float val = acc[i][j] + bias[n];
            int t = n >> 8;
            int rem = n & 255;
            int h = rem >> 4, d = rem & 15;
            float* dst = (t == 0) ? g_q : (t == 1) ? g_k : g_v;
            dst[((((size_t)b * HH + h) * NN + nq) << 4) + d] = val;
        }
    }
}

__global__ void gemm_proj_kernel(const float* __restrict__ W,
                                 const float* __restrict__ bias,
                                 float* __restrict__ out) {
    const int K = CC, Nn = CC;  // 256, 256
    const float* A = g_o;
    __shared__ float As[16][64];
    __shared__ float Bs[16][64];
    int tid = threadIdx.x;
    int tx = tid & 15, ty = tid >> 4;
    int m0 = blockIdx.y * 64, n0 = blockIdx.x * 64;
    int ar = tid >> 2, ac = (tid & 3) << 2;
    int br = tid >> 4, bc = (tid & 15) << 2;
    float acc[4][4] = {};
    for (int k0 = 0; k0 < K; k0 += 16) {
        float4 a = *(const float4*)&A[(size_t)(m0 + ar) * K + k0 + ac];
        As[ac + 0][ar] = a.x; As[ac + 1][ar] = a.y;
        As[ac + 2][ar] = a.z; As[ac + 3][ar] = a.w;
        *(float4*)&Bs[br][bc] = *(const float4*)&W[(size_t)(k0 + br) * Nn + n0 + bc];
        __syncthreads();
#pragma unroll
        for (int k = 0; k < 16; k++) {
            float ra[4], rb[4];
            *(float4*)ra = *(const float4*)&As[k][ty * 4];
            *(float4*)rb = *(const float4*)&Bs[k][tx * 4];
#pragma unroll
            for (int i = 0; i < 4; i++)
#pragma unroll
                for (int j = 0; j < 4; j++)
                    acc[i][j] += ra[i] * rb[j];
        }
        __syncthreads();
    }
#pragma unroll
    for (int i = 0; i < 4; i++) {
        int m = m0 + ty * 4 + i;
#pragma unroll
        for (int j = 0; j < 4; j++) {
            int n = n0 + tx * 4 + j;
            out[(size_t)m * Nn + n] = acc[i][j] + bias[n];
        }
    }
}

// ---------------------------------------------------------------------------
// Flash attention, no scaling. One thread = one query row (D=16 in regs).
// K/V tiles of 128 rows staged in smem; all threads walk the same key index
// together -> broadcast LDS (conflict-free). Online softmax with branched
// rescale (rescale only on new max).
// grid: (N/128, B*H), block: 128
// ---------------------------------------------------------------------------
__global__ void attn_kernel() {
    constexpr int KT = 128;
    __shared__ float4 sK[KT * 4];
    __shared__ float4 sV[KT * 4];
    int bh = blockIdx.y;
    int q0 = blockIdx.x * 128;
    int tid = threadIdx.x;
    const float* Qb = g_q + (size_t)bh * NN * DD;
    const float* Kb = g_k + (size_t)bh * NN * DD;
    const float* Vb = g_v + (size_t)bh * NN * DD;

    float4 q[4];
    {
        const float4* qr = (const float4*)(Qb + (size_t)(q0 + tid) * DD);
        q[0] = qr[0]; q[1] = qr[1]; q[2] = qr[2]; q[3] = qr[3];
    }
    float mmax = -INFINITY, l = 0.f;
    float acc[16] = {};

    for (int k0 = 0; k0 < NN; k0 += KT) {
        __syncthreads();
        const float4* Kg = (const float4*)(Kb + (size_t)k0 * DD);
        const float4* Vg = (const float4*)(Vb + (size_t)k0 * DD);
#pragma unroll
        for (int i = 0; i < 4; i++) {
            sK[tid + i * 128] = Kg[tid + i * 128];
            sV[tid + i * 128] = Vg[tid + i * 128];
        }
        __syncthreads();
#pragma unroll 2
        for (int kk = 0; kk < KT; kk++) {
            float4 ka = sK[kk * 4 + 0];
            float4 kb = sK[kk * 4 + 1];
            float4 kc = sK[kk * 4 + 2];
            float4 kd = sK[kk * 4 + 3];
            float s = q[0].x * ka.x + q[0].y * ka.y + q[0].z * ka.z + q[0].w * ka.w
                    + q[1].x * kb.x + q[1].y * kb.y + q[1].z * kb.z + q[1].w * kb.w
                    + q[2].x * kc.x + q[2].y * kc.y + q[2].z * kc.z + q[2].w * kc.w
                    + q[3].x * kd.x + q[3].y * kd.y + q[3].z * kd.z + q[3].w * kd.w;
            if (s > mmax) {
                float corr = __expf(mmax - s);  // 0 on first key (mmax = -inf)
                mmax = s;
                l *= corr;
#pragma unroll
                for (int d = 0; d < 16; d++) acc[d] *= corr;
            }
            float e = __expf(s - mmax);
            l += e;
            float4 va = sV[kk * 4 + 0];
            float4 vb = sV[kk * 4 + 1];
            float4 vc = sV[kk * 4 + 2];
            float4 vd = sV[kk * 4 + 3];
            acc[0]  += e * va.x; acc[1]  += e * va.y; acc[2]  += e * va.z; acc[3]  += e * va.w;
            acc[4]  += e * vb.x; acc[5]  += e * vb.y; acc[6]  += e * vb.z; acc[7]  += e * vb.w;
            acc[8]  += e * vc.x; acc[9]  += e * vc.y; acc[10] += e * vc.z; acc[11] += e * vc.w;
            acc[12] += e * vd.x; acc[13] += e * vd.y; acc[14] += e * vd.z; acc[15] += e * vd.w;
        }
    }

    int b = bh / HH, h = bh % HH;
    float inv = 1.0f / l;
#pragma unroll
    for (int d = 0; d < 16; d++) acc[d] *= inv;
    float4* o4 = (float4*)(g_o + ((size_t)(b * NN + q0 + tid) * CC) + h * DD);
    o4[0] = *(float4*)&acc[0];
    o4[1] = *(float4*)&acc[4];
    o4[2] = *(float4*)&acc[8];
    o4[3] = *(float4*)&acc[12];
}

// ---------------------------------------------------------------------------
extern "C" void kernel_launch(void* const* d_in, const int* in_sizes, int n_in,
                              void* d_out, int out_size) {
    const float* x      = (const float*)d_in[0];
    const float* w_qkv  = (const float*)d_in[1];
    const float* b_qkv  = (const float*)d_in[2];
    const float* w_proj = (const float*)d_in[3];
    const float* b_proj = (const float*)d_in[4];
    float* out = (float*)d_out;

    dim3 g1(12, 128);              // 768/64, 8192/64
    gemm_qkv_kernel<<<g1, 256>>>(x, w_qkv, b_qkv);

    dim3 g2(NN / 128, BB * HH);    // (16, 64)
    attn_kernel<<<g2, 128>>>();

    dim3 g3(4, 128);               // 256/64, 8192/64
    gemm_proj_kernel<<<g3, 256>>>(w_proj, b_proj, out);
}